// round 13
// baseline (speedup 1.0000x reference)
#include <cuda_runtime.h>
#include <cstdint>

typedef unsigned long long ull;

#define NB 128
#define NT 4096
#define K1_NTH 128
#define NCHUNK 8            // CTAs per batch (grid 1024 <= 148*8 resident slots)
#define TOKC 512            // tokens per CTA

__device__ float g_scratch[NB * NCHUNK * 18];   // [cta][sum, ctx16]
__device__ int   g_cnt1[NB];
__device__ int   g_cnt2[NB];

__constant__ ull   cW2p[32 * 8];   // W2 rows as packed float pairs
__constant__ float cvw[32];        // v_w

__device__ __forceinline__ float ex2f_(float x) {
    float y; asm("ex2.approx.f32 %0, %1;" : "=f"(y) : "f"(x)); return y;
}
__device__ __forceinline__ float rcpf_(float x) {
    float y; asm("rcp.approx.f32 %0, %1;" : "=f"(y) : "f"(x)); return y;
}
__device__ __forceinline__ float tanhf_(float x) {
    float y; asm("tanh.approx.f32 %0, %1;" : "=f"(y) : "f"(x)); return y;
}
__device__ __forceinline__ void pfma(ull& d, ull a, ull b) {
    asm("fma.rn.f32x2 %0, %1, %2, %0;" : "+l"(d) : "l"(a), "l"(b));
}
__device__ __forceinline__ ull padd(ull a, ull b) {
    ull d; asm("add.rn.f32x2 %0, %1, %2;" : "=l"(d) : "l"(a), "l"(b)); return d;
}
__device__ __forceinline__ ull pack2(float a, float b) {
    ull p; asm("mov.b64 %0, {%1, %2};" : "=l"(p) : "f"(a), "f"(b)); return p;
}
__device__ __forceinline__ float2 unpack2(ull p) {
    float2 r; asm("mov.b64 {%0, %1}, %2;" : "=f"(r.x), "=f"(r.y) : "l"(p)); return r;
}
__device__ __forceinline__ void red_release_add(int* p, int v) {
    asm volatile("red.release.gpu.global.add.s32 [%0], %1;" :: "l"(p), "r"(v) : "memory");
}
__device__ __forceinline__ int ld_acquire(const int* p) {
    int v; asm volatile("ld.acquire.gpu.global.s32 %0, [%1];" : "=r"(v) : "l"(p) : "memory");
    return v;
}
__device__ __forceinline__ uint32_t s2u(const void* p) {
    uint32_t a;
    asm("{ .reg .u64 t; cvta.to.shared.u64 t, %1; cvt.u32.u64 %0, t; }"
        : "=r"(a) : "l"(p));
    return a;
}
__device__ __forceinline__ void cp16(uint32_t dst, const void* g) {
    asm volatile("cp.async.cg.shared.global [%0], [%1], 16;" :: "r"(dst), "l"(g));
}
__device__ __forceinline__ void cpcommit() {
    asm volatile("cp.async.commit_group;");
}
__device__ __forceinline__ void cpwait0() {
    asm volatile("cp.async.wait_group 0;");
}

// swizzled offset of (token, quarter) inside a 64-token x 64B tile buffer
__device__ __forceinline__ uint32_t qoff(int t, int q) {
    return (uint32_t)(t * 64 + ((q ^ ((t >> 1) & 3)) * 16));
}

__device__ __forceinline__ void stage_tile(uint32_t sw, const float* gsrc, int lane) {
    #pragma unroll
    for (int k = 0; k < 8; k++) {
        const int c = lane + k * 32;
        cp16(sw + qoff(c >> 2, c & 3), gsrc + (size_t)c * 4);
    }
    cpcommit();
}

__device__ __forceinline__ void read_pair(const char* buf, int lane, ull* ka, ull* kb) {
    #pragma unroll
    for (int q = 0; q < 4; q++) {
        ulonglong2 va = *reinterpret_cast<const ulonglong2*>(buf + qoff(lane, q));
        ka[2*q] = va.x; ka[2*q+1] = va.y;
        ulonglong2 vb_ = *reinterpret_cast<const ulonglong2*>(buf + qoff(lane + 32, q));
        kb[2*q] = vb_.x; kb[2*q+1] = vb_.y;
    }
}

__global__ void __launch_bounds__(K1_NTH, 8)
attn_fused(const float* __restrict__ query,   // [B,1,16]
           const float* __restrict__ key,     // [B,T,16]
           const float* __restrict__ value,   // [B,T,16]
           const float* __restrict__ W1,      // [32,16]
           const float* __restrict__ bias,    // scalar
           const float* __restrict__ v_b,     // [1]
           float* __restrict__ out_ctx,       // [B,16]
           float* __restrict__ out_attn)      // [B,T]
{
    const int cta   = blockIdx.x;
    const int b     = cta >> 3;
    const int chunk = cta & 7;
    const int base  = chunk * TOKC;
    const int tid   = threadIdx.x;
    const int lane  = tid & 31;
    const int wid   = tid >> 5;

    __shared__ __align__(16) char swz[4][4096];   // per-warp staging buffers
    __shared__ ull   sqp[32];        // (qproj_w + bias, 0) packed
    __shared__ float sred[4 * 17];
    __shared__ float sbc[1];         // broadcast: global inv

    const uint32_t sw   = s2u(swz[wid]);
    const char*    bufc = swz[wid];

    const int tile0 = base + wid * 64;          // pass 0 tokens
    const int tile1 = base + wid * 64 + 256;    // pass 1 tokens
    const float* krow = key   + (size_t)b * NT * 16;
    const float* vrow = value + (size_t)b * NT * 16;

    // G1: key tile 0 — issue immediately
    stage_tile(sw, krow + (size_t)tile0 * 16, lane);

    // q projection (W2/v_w come from __constant__)
    if (tid < 32) {
        const int w = tid;
        float acc = *bias;
        #pragma unroll
        for (int d = 0; d < 16; d++)
            acc = fmaf(query[b * 16 + d], W1[w * 16 + d], acc);
        sqp[w] = pack2(acc, 0.0f);
    }
    __syncthreads();

    const float vb = *v_b;
    const float L  = 1.4426950408889634f;

    // ---------- Scores + inline exp (no max pass: |score| <= |v_b|+sum|v_w|) ----
    float e_[4];
    float csum = 0.0f;

    #pragma unroll
    for (int jp = 0; jp < 2; jp++) {
        cpwait0();
        __syncwarp();
        ull ka[8], kb[8];
        read_pair(bufc, lane, ka, kb);
        __syncwarp();

        if (jp == 0)
            stage_tile(sw, krow + (size_t)tile1 * 16, lane);   // G2: key tile 1
        else
            stage_tile(sw, vrow + (size_t)tile0 * 16, lane);   // G3: value tile A

        float a0 = vb, a1 = vb;
        #pragma unroll 4
        for (int w = 0; w < 32; w++) {
            // 4 independent FMA chains (depth 8) instead of 2 (depth 16)
            ull a0a = sqp[w];
            ull a1a = a0a;
            ull a0b = 0ull;
            ull a1b = 0ull;
            const ull* wr = &cW2p[w * 8];
            pfma(a0a, ka[0], wr[0]); pfma(a1a, kb[0], wr[0]);
            pfma(a0b, ka[1], wr[1]); pfma(a1b, kb[1], wr[1]);
            pfma(a0a, ka[2], wr[2]); pfma(a1a, kb[2], wr[2]);
            pfma(a0b, ka[3], wr[3]); pfma(a1b, kb[3], wr[3]);
            pfma(a0a, ka[4], wr[4]); pfma(a1a, kb[4], wr[4]);
            pfma(a0b, ka[5], wr[5]); pfma(a1b, kb[5], wr[5]);
            pfma(a0a, ka[6], wr[6]); pfma(a1a, kb[6], wr[6]);
            pfma(a0b, ka[7], wr[7]); pfma(a1b, kb[7], wr[7]);

            const float2 h0 = unpack2(padd(a0a, a0b));
            const float2 h1 = unpack2(padd(a1a, a1b));
            const float t0h = tanhf_(h0.x + h0.y);
            const float t1h = tanhf_(h1.x + h1.y);
            const float vw = cvw[w];
            a0 = fmaf(vw, t0h, a0);
            a1 = fmaf(vw, t1h, a1);
        }
        const float e0 = ex2f_(a0 * L);    // exp(score), unnormalized — safe
        const float e1 = ex2f_(a1 * L);
        e_[2 * jp + 0] = e0;
        e_[2 * jp + 1] = e1;
        csum += e0 + e1;
    }

    // ---------- Value accumulation (two tiles, pipelined) ----------
    ull cv[8];
    #pragma unroll
    for (int i = 0; i < 8; i++) cv[i] = 0ull;

    {   // value tile A (tokens tile0+lane, tile0+lane+32)
        cpwait0();
        __syncwarp();
        ull va[8], vbr[8];
        read_pair(bufc, lane, va, vbr);
        __syncwarp();
        stage_tile(sw, vrow + (size_t)tile1 * 16, lane);       // G4: value tile B

        const ull ee0 = pack2(e_[0], e_[0]);
        const ull ee1 = pack2(e_[1], e_[1]);
        #pragma unroll
        for (int i = 0; i < 8; i++) {
            pfma(cv[i], ee0, va[i]);
            pfma(cv[i], ee1, vbr[i]);
        }
    }
    {   // value tile B (tokens tile1+lane, tile1+lane+32)
        cpwait0();
        __syncwarp();
        ull va[8], vbr[8];
        read_pair(bufc, lane, va, vbr);

        const ull ee2 = pack2(e_[2], e_[2]);
        const ull ee3 = pack2(e_[3], e_[3]);
        #pragma unroll
        for (int i = 0; i < 8; i++) {
            pfma(cv[i], ee2, va[i]);
            pfma(cv[i], ee3, vbr[i]);
        }
    }

    float cvf[16];
    #pragma unroll
    for (int i = 0; i < 8; i++) {
        float2 u = unpack2(cv[i]);
        cvf[2*i] = u.x; cvf[2*i+1] = u.y;
    }

    // ---------- Deterministic 17-value reduction over 4 warps ----------
    #pragma unroll
    for (int o = 16; o > 0; o >>= 1) {
        csum += __shfl_xor_sync(0xffffffffu, csum, o);
        #pragma unroll
        for (int i = 0; i < 16; i++)
            cvf[i] += __shfl_xor_sync(0xffffffffu, cvf[i], o);
    }
    if (lane == 0) {
        sred[wid * 17] = csum;
        #pragma unroll
        for (int i = 0; i < 16; i++) sred[wid * 17 + 1 + i] = cvf[i];
    }
    __syncthreads();
    if (tid < 17) {
        float a = sred[tid];
        #pragma unroll
        for (int w = 1; w < 4; w++) a += sred[w * 17 + tid];
        g_scratch[cta * 18 + tid] = a;       // [0]=sum, [1..16]=ctx
    }
    __syncthreads();

    // ---------- Cross-CTA combine: arrive + spin (sum only) ----------
    if (tid == 0) {
        red_release_add(&g_cnt1[b], 1);
        while (ld_acquire(&g_cnt1[b]) < NCHUNK) __nanosleep(32);
    }
    __syncthreads();

    if (tid == 0) {
        const float* gs = g_scratch + b * (NCHUNK * 18);
        float total = 0.0f;
        #pragma unroll
        for (int c = 0; c < NCHUNK; c++) total += gs[c * 18];
        sbc[0] = rcpf_(total);
    }
    __syncthreads();
    const float inv = sbc[0];

    if (chunk == 0 && tid < 16) {
        const float* gs = g_scratch + b * (NCHUNK * 18);
        float acc = 0.0f;
        #pragma unroll
        for (int c = 0; c < NCHUNK; c++) acc += gs[c * 18 + 1 + tid];
        out_ctx[b * 16 + tid] = acc * inv;
    }

    float* ao = out_attn + (size_t)b * NT;
    ao[tile0 + lane]      = e_[0] * inv;
    ao[tile0 + lane + 32] = e_[1] * inv;
    ao[tile1 + lane]      = e_[2] * inv;
    ao[tile1 + lane + 32] = e_[3] * inv;

    // ---------- Counter reset for graph replay ----------
    __syncthreads();
    if (tid == 0) {
        if (atomicAdd(&g_cnt2[b], 1) == NCHUNK - 1) {
            g_cnt1[b] = 0;
            __threadfence();
            g_cnt2[b] = 0;
        }
    }
}

extern "C" void kernel_launch(void* const* d_in, const int* in_sizes, int n_in,
                              void* d_out, int out_size) {
    const float* query = (const float*)d_in[0];
    const float* key   = (const float*)d_in[1];
    const float* value = (const float*)d_in[2];
    const float* W1    = (const float*)d_in[3];
    const float* W2    = (const float*)d_in[4];
    const float* bias  = (const float*)d_in[5];
    const float* v_w   = (const float*)d_in[6];
    const float* v_b   = (const float*)d_in[7];

    float* out_ctx  = (float*)d_out;            // [B,1,16]
    float* out_attn = (float*)d_out + NB * 16;  // [B,T]

    cudaMemcpyToSymbolAsync(cW2p, W2, 32 * 16 * sizeof(float), 0,
                            cudaMemcpyDeviceToDevice);
    cudaMemcpyToSymbolAsync(cvw, v_w, 32 * sizeof(float), 0,
                            cudaMemcpyDeviceToDevice);

    attn_fused<<<NB * NCHUNK, K1_NTH>>>(query, key, value, W1,
                                        bias, v_b, out_ctx, out_attn);
}

// round 14
// speedup vs baseline: 1.0115x; 1.0115x over previous
#include <cuda_runtime.h>
#include <cstdint>

typedef unsigned long long ull;

#define NB 128
#define NT 4096
#define K1_NTH 128
#define NCHUNK 8            // CTAs per batch (grid 1024 <= 148*8 resident slots)
#define TOKC 512            // tokens per CTA

__device__ float g_scratch[NB * NCHUNK * 18];   // [cta][sum, ctx16]
__device__ int   g_cnt1[NB];                    // sum-ready arrivals
__device__ int   g_cnt2[NB];                    // full-done arrivals

__constant__ ull cW2p[32 * 8];   // W2 rows as packed float pairs

__device__ __forceinline__ float ex2f_(float x) {
    float y; asm("ex2.approx.f32 %0, %1;" : "=f"(y) : "f"(x)); return y;
}
__device__ __forceinline__ float rcpf_(float x) {
    float y; asm("rcp.approx.f32 %0, %1;" : "=f"(y) : "f"(x)); return y;
}
__device__ __forceinline__ float tanhf_(float x) {
    float y; asm("tanh.approx.f32 %0, %1;" : "=f"(y) : "f"(x)); return y;
}
__device__ __forceinline__ void pfma(ull& d, ull a, ull b) {
    asm("fma.rn.f32x2 %0, %1, %2, %0;" : "+l"(d) : "l"(a), "l"(b));
}
__device__ __forceinline__ ull pack2(float a, float b) {
    ull p; asm("mov.b64 %0, {%1, %2};" : "=l"(p) : "f"(a), "f"(b)); return p;
}
__device__ __forceinline__ float2 unpack2(ull p) {
    float2 r; asm("mov.b64 {%0, %1}, %2;" : "=f"(r.x), "=f"(r.y) : "l"(p)); return r;
}
__device__ __forceinline__ void red_release_add(int* p, int v) {
    asm volatile("red.release.gpu.global.add.s32 [%0], %1;" :: "l"(p), "r"(v) : "memory");
}
__device__ __forceinline__ int ld_acquire(const int* p) {
    int v; asm volatile("ld.acquire.gpu.global.s32 %0, [%1];" : "=r"(v) : "l"(p) : "memory");
    return v;
}
__device__ __forceinline__ uint32_t s2u(const void* p) {
    uint32_t a;
    asm("{ .reg .u64 t; cvta.to.shared.u64 t, %1; cvt.u32.u64 %0, t; }"
        : "=r"(a) : "l"(p));
    return a;
}
__device__ __forceinline__ void cp16(uint32_t dst, const void* g) {
    asm volatile("cp.async.cg.shared.global [%0], [%1], 16;" :: "r"(dst), "l"(g));
}
__device__ __forceinline__ void cpcommit() {
    asm volatile("cp.async.commit_group;");
}
__device__ __forceinline__ void cpwait0() {
    asm volatile("cp.async.wait_group 0;");
}

// swizzled offset of (token, quarter) inside a 64-token x 64B tile buffer
__device__ __forceinline__ uint32_t qoff(int t, int q) {
    return (uint32_t)(t * 64 + ((q ^ ((t >> 1) & 3)) * 16));
}

__device__ __forceinline__ void stage_tile(uint32_t sw, const float* gsrc, int lane) {
    #pragma unroll
    for (int k = 0; k < 8; k++) {
        const int c = lane + k * 32;
        cp16(sw + qoff(c >> 2, c & 3), gsrc + (size_t)c * 4);
    }
    cpcommit();
}

__device__ __forceinline__ void read_pair(const char* buf, int lane, ull* ka, ull* kb) {
    #pragma unroll
    for (int q = 0; q < 4; q++) {
        ulonglong2 va = *reinterpret_cast<const ulonglong2*>(buf + qoff(lane, q));
        ka[2*q] = va.x; ka[2*q+1] = va.y;
        ulonglong2 vb_ = *reinterpret_cast<const ulonglong2*>(buf + qoff(lane + 32, q));
        kb[2*q] = vb_.x; kb[2*q+1] = vb_.y;
    }
}

__global__ void __launch_bounds__(K1_NTH, 8)
attn_fused(const float* __restrict__ query,   // [B,1,16]
           const float* __restrict__ key,     // [B,T,16]
           const float* __restrict__ value,   // [B,T,16]
           const float* __restrict__ W1,      // [32,16]
           const float* __restrict__ bias,    // scalar
           const float* __restrict__ v_w,     // [1,32]
           const float* __restrict__ v_b,     // [1]
           float* __restrict__ out_ctx,       // [B,16]
           float* __restrict__ out_attn)      // [B,T]
{
    const int cta   = blockIdx.x;
    const int b     = cta >> 3;
    const int chunk = cta & 7;
    const int base  = chunk * TOKC;
    const int tid   = threadIdx.x;
    const int lane  = tid & 31;
    const int wid   = tid >> 5;

    __shared__ __align__(16) char swz[4][4096];   // per-warp staging buffers
    __shared__ ulonglong2 scv[32];   // .x=(qproj+bias, 0) packed, .y lo = L*v_w[w]
    __shared__ float ssum[4];        // per-warp csum partials
    __shared__ float sred[4 * 16];   // ctx cross-warp reduction
    __shared__ float sbc[1];         // broadcast: global inv

    const uint32_t sw   = s2u(swz[wid]);
    const char*    bufc = swz[wid];

    const int tile0 = base + wid * 64;          // pass 0 tokens
    const int tile1 = base + wid * 64 + 256;    // pass 1 tokens
    const float* krow = key   + (size_t)b * NT * 16;
    const float* vrow = value + (size_t)b * NT * 16;
    const float L = 1.4426950408889634f;

    // G1: key tile 0 — issue immediately
    stage_tile(sw, krow + (size_t)tile0 * 16, lane);

    // q projection + v_w staging (W2 comes from __constant__)
    if (tid < 32) {
        const int w = tid;
        float acc = *bias;
        #pragma unroll
        for (int d = 0; d < 16; d++)
            acc = fmaf(query[b * 16 + d], W1[w * 16 + d], acc);
        scv[w].x = pack2(acc, 0.0f);
        scv[w].y = pack2(L * v_w[w], 0.0f);     // pre-scaled by log2(e)
    }
    __syncthreads();

    const float vbL = v_b[0] * L;

    // ---------- Phase A: scores + inline exp (no max pass: bounded scores) ----
    float e_[4];
    float csum = 0.0f;

    #pragma unroll
    for (int jp = 0; jp < 2; jp++) {
        cpwait0();
        __syncwarp();
        ull ka[8], kb[8];
        read_pair(bufc, lane, ka, kb);
        __syncwarp();

        if (jp == 0)
            stage_tile(sw, krow + (size_t)tile1 * 16, lane);   // G2: key tile 1
        else
            stage_tile(sw, vrow + (size_t)tile0 * 16, lane);   // G3: value tile A

        float a0 = vbL, a1 = vbL;
        #pragma unroll 4
        for (int w = 0; w < 32; w++) {
            const ulonglong2 cc = scv[w];      // one LDS.128: qproj pair + L*v_w
            ull acc0 = cc.x;
            ull acc1 = acc0;
            const float vwL = unpack2(cc.y).x;
            const ull* wr = &cW2p[w * 8];
            pfma(acc0, ka[0], wr[0]); pfma(acc1, kb[0], wr[0]);
            pfma(acc0, ka[1], wr[1]); pfma(acc1, kb[1], wr[1]);
            pfma(acc0, ka[2], wr[2]); pfma(acc1, kb[2], wr[2]);
            pfma(acc0, ka[3], wr[3]); pfma(acc1, kb[3], wr[3]);
            pfma(acc0, ka[4], wr[4]); pfma(acc1, kb[4], wr[4]);
            pfma(acc0, ka[5], wr[5]); pfma(acc1, kb[5], wr[5]);
            pfma(acc0, ka[6], wr[6]); pfma(acc1, kb[6], wr[6]);
            pfma(acc0, ka[7], wr[7]); pfma(acc1, kb[7], wr[7]);

            const float2 h0 = unpack2(acc0);
            const float2 h1 = unpack2(acc1);
            const float t0h = tanhf_(h0.x + h0.y);
            const float t1h = tanhf_(h1.x + h1.y);
            a0 = fmaf(vwL, t0h, a0);
            a1 = fmaf(vwL, t1h, a1);
        }
        const float e0 = ex2f_(a0);        // exp(score), L pre-folded
        const float e1 = ex2f_(a1);
        e_[2 * jp + 0] = e0;
        e_[2 * jp + 1] = e1;
        csum += e0 + e1;
    }

    // ---------- EARLY publish of this CTA's sum (hides sibling skew) ----------
    {
        float cs = csum;
        #pragma unroll
        for (int o = 16; o > 0; o >>= 1)
            cs += __shfl_xor_sync(0xffffffffu, cs, o);
        if (lane == 0) ssum[wid] = cs;
    }
    __syncthreads();
    if (tid == 0) {
        const float total_cta = ssum[0] + ssum[1] + ssum[2] + ssum[3];
        g_scratch[cta * 18] = total_cta;
        red_release_add(&g_cnt1[b], 1);      // arrive: sum ready
    }

    // ---------- Value accumulation (two tiles, pipelined) ----------
    ull cv[8];
    #pragma unroll
    for (int i = 0; i < 8; i++) cv[i] = 0ull;

    {   // value tile A (tokens tile0+lane, tile0+lane+32)
        cpwait0();
        __syncwarp();
        ull va[8], vbr[8];
        read_pair(bufc, lane, va, vbr);
        __syncwarp();
        stage_tile(sw, vrow + (size_t)tile1 * 16, lane);       // G4: value tile B

        const ull ee0 = pack2(e_[0], e_[0]);
        const ull ee1 = pack2(e_[1], e_[1]);
        #pragma unroll
        for (int i = 0; i < 8; i++) {
            pfma(cv[i], ee0, va[i]);
            pfma(cv[i], ee1, vbr[i]);
        }
    }
    {   // value tile B (tokens tile1+lane, tile1+lane+32)
        cpwait0();
        __syncwarp();
        ull va[8], vbr[8];
        read_pair(bufc, lane, va, vbr);

        const ull ee2 = pack2(e_[2], e_[2]);
        const ull ee3 = pack2(e_[3], e_[3]);
        #pragma unroll
        for (int i = 0; i < 8; i++) {
            pfma(cv[i], ee2, va[i]);
            pfma(cv[i], ee3, vbr[i]);
        }
    }

    float cvf[16];
    #pragma unroll
    for (int i = 0; i < 8; i++) {
        float2 u = unpack2(cv[i]);
        cvf[2*i] = u.x; cvf[2*i+1] = u.y;
    }

    // ---------- Deterministic ctx reduction over 4 warps ----------
    #pragma unroll
    for (int o = 16; o > 0; o >>= 1) {
        #pragma unroll
        for (int i = 0; i < 16; i++)
            cvf[i] += __shfl_xor_sync(0xffffffffu, cvf[i], o);
    }
    if (lane == 0) {
        #pragma unroll
        for (int i = 0; i < 16; i++) sred[wid * 16 + i] = cvf[i];
    }
    __syncthreads();
    if (tid < 16) {
        float a = sred[tid];
        #pragma unroll
        for (int w = 1; w < 4; w++) a += sred[w * 16 + tid];
        g_scratch[cta * 18 + 1 + tid] = a;   // ctx partial
    }
    __syncthreads();

    // ---------- Spin on sums (usually already satisfied) ----------
    if (tid == 0) {
        while (ld_acquire(&g_cnt1[b]) < NCHUNK) __nanosleep(32);
        const float* gs = g_scratch + b * (NCHUNK * 18);
        float total = 0.0f;
        #pragma unroll
        for (int c = 0; c < NCHUNK; c++) total += gs[c * 18];   // fixed order
        sbc[0] = rcpf_(total);
    }
    __syncthreads();
    const float inv = sbc[0];

    float* ao = out_attn + (size_t)b * NT;
    ao[tile0 + lane]      = e_[0] * inv;
    ao[tile0 + lane + 32] = e_[1] * inv;
    ao[tile1 + lane]      = e_[2] * inv;
    ao[tile1 + lane + 32] = e_[3] * inv;

    // ---------- Full-done arrival (after cnt1 spin passed: reset-safe) ----------
    __syncthreads();
    if (tid == 0) red_release_add(&g_cnt2[b], 1);

    // chunk 0 combines ctx partials and resets counters
    if (chunk == 0) {
        if (tid == 0) {
            while (ld_acquire(&g_cnt2[b]) < NCHUNK) __nanosleep(32);
        }
        __syncthreads();
        if (tid < 16) {
            const float* gs = g_scratch + b * (NCHUNK * 18);
            float acc = 0.0f;
            #pragma unroll
            for (int c = 0; c < NCHUNK; c++) acc += gs[c * 18 + 1 + tid];
            out_ctx[b * 16 + tid] = acc * inv;
        }
        __syncthreads();
        if (tid == 0) {        // all siblings passed both counters by now
            g_cnt1[b] = 0;
            __threadfence();
            g_cnt2[b] = 0;
        }
    }
}

extern "C" void kernel_launch(void* const* d_in, const int* in_sizes, int n_in,
                              void* d_out, int out_size) {
    const float* query = (const float*)d_in[0];
    const float* key   = (const float*)d_in[1];
    const float* value = (const float*)d_in[2];
    const float* W1    = (const float*)d_in[3];
    const float* W2    = (const float*)d_in[4];
    const float* bias  = (const float*)d_in[5];
    const float* v_w   = (const float*)d_in[6];
    const float* v_b   = (const float*)d_in[7];

    float* out_ctx  = (float*)d_out;            // [B,1,16]
    float* out_attn = (float*)d_out + NB * 16;  // [B,T]

    // Single constant upload (W2 only; v_w handled in-kernel via smem)
    cudaMemcpyToSymbolAsync(cW2p, W2, 32 * 16 * sizeof(float), 0,
                            cudaMemcpyDeviceToDevice);

    attn_fused<<<NB * NCHUNK, K1_NTH>>>(query, key, value, W1,
                                        bias, v_w, v_b, out_ctx, out_attn);
}

// round 15
// speedup vs baseline: 1.1014x; 1.0889x over previous
#include <cuda_runtime.h>
#include <cstdint>

typedef unsigned long long ull;

#define NB 128
#define NT 4096
#define K1_NTH 128
#define NCHUNK 8            // CTAs per batch (grid 1024 <= 148*8 resident slots)
#define TOKC 512            // tokens per CTA

__device__ float g_scratch[NB * NCHUNK * 18];   // [cta][sum, ctx16]
__device__ int   g_cnt1[NB];                    // sum-ready arrivals
__device__ int   g_cnt2[NB];                    // full-done arrivals

__constant__ ulonglong2 cW2q[32 * 4];   // W2 rows as 128-bit packed quads

__device__ __forceinline__ float ex2f_(float x) {
    float y; asm("ex2.approx.f32 %0, %1;" : "=f"(y) : "f"(x)); return y;
}
__device__ __forceinline__ float rcpf_(float x) {
    float y; asm("rcp.approx.f32 %0, %1;" : "=f"(y) : "f"(x)); return y;
}
__device__ __forceinline__ float tanhf_(float x) {
    float y; asm("tanh.approx.f32 %0, %1;" : "=f"(y) : "f"(x)); return y;
}
__device__ __forceinline__ void pfma(ull& d, ull a, ull b) {
    asm("fma.rn.f32x2 %0, %1, %2, %0;" : "+l"(d) : "l"(a), "l"(b));
}
__device__ __forceinline__ ull pack2(float a, float b) {
    ull p; asm("mov.b64 %0, {%1, %2};" : "=l"(p) : "f"(a), "f"(b)); return p;
}
__device__ __forceinline__ float2 unpack2(ull p) {
    float2 r; asm("mov.b64 {%0, %1}, %2;" : "=f"(r.x), "=f"(r.y) : "l"(p)); return r;
}
__device__ __forceinline__ void red_release_add(int* p, int v) {
    asm volatile("red.release.gpu.global.add.s32 [%0], %1;" :: "l"(p), "r"(v) : "memory");
}
__device__ __forceinline__ int ld_acquire(const int* p) {
    int v; asm volatile("ld.acquire.gpu.global.s32 %0, [%1];" : "=r"(v) : "l"(p) : "memory");
    return v;
}
__device__ __forceinline__ uint32_t s2u(const void* p) {
    uint32_t a;
    asm("{ .reg .u64 t; cvta.to.shared.u64 t, %1; cvt.u32.u64 %0, t; }"
        : "=r"(a) : "l"(p));
    return a;
}
__device__ __forceinline__ void cp16(uint32_t dst, const void* g) {
    asm volatile("cp.async.cg.shared.global [%0], [%1], 16;" :: "r"(dst), "l"(g));
}
__device__ __forceinline__ void cpcommit() {
    asm volatile("cp.async.commit_group;");
}
__device__ __forceinline__ void cpwait0() {
    asm volatile("cp.async.wait_group 0;");
}

// swizzled offset of (token, quarter) inside a 64-token x 64B tile buffer
__device__ __forceinline__ uint32_t qoff(int t, int q) {
    return (uint32_t)(t * 64 + ((q ^ ((t >> 1) & 3)) * 16));
}

__device__ __forceinline__ void stage_tile(uint32_t sw, const float* gsrc, int lane) {
    #pragma unroll
    for (int k = 0; k < 8; k++) {
        const int c = lane + k * 32;
        cp16(sw + qoff(c >> 2, c & 3), gsrc + (size_t)c * 4);
    }
    cpcommit();
}

__device__ __forceinline__ void read_pair(const char* buf, int lane, ull* ka, ull* kb) {
    #pragma unroll
    for (int q = 0; q < 4; q++) {
        ulonglong2 va = *reinterpret_cast<const ulonglong2*>(buf + qoff(lane, q));
        ka[2*q] = va.x; ka[2*q+1] = va.y;
        ulonglong2 vb_ = *reinterpret_cast<const ulonglong2*>(buf + qoff(lane + 32, q));
        kb[2*q] = vb_.x; kb[2*q+1] = vb_.y;
    }
}

__global__ void __launch_bounds__(K1_NTH, 8)
attn_fused(const float* __restrict__ query,   // [B,1,16]
           const float* __restrict__ key,     // [B,T,16]
           const float* __restrict__ value,   // [B,T,16]
           const float* __restrict__ W1,      // [32,16]
           const float* __restrict__ bias,    // scalar
           const float* __restrict__ v_w,     // [1,32]
           const float* __restrict__ v_b,     // [1]
           float* __restrict__ out_ctx,       // [B,16]
           float* __restrict__ out_attn)      // [B,T]
{
    const int cta   = blockIdx.x;
    const int b     = cta >> 3;
    const int chunk = cta & 7;
    const int base  = chunk * TOKC;
    const int tid   = threadIdx.x;
    const int lane  = tid & 31;
    const int wid   = tid >> 5;

    __shared__ __align__(16) char swz[4][4096];   // per-warp staging buffers
    __shared__ ulonglong2 scv[32];   // .x=(qproj+bias, 0) packed, .y lo = L*v_w[w]
    __shared__ float ssum[4];        // per-warp csum partials
    __shared__ float sred[4 * 16];   // ctx cross-warp reduction
    __shared__ float sbc[1];         // broadcast: global inv
    __shared__ int   slast;          // last-arriver flag

    const uint32_t sw   = s2u(swz[wid]);
    const char*    bufc = swz[wid];

    const int tile0 = base + wid * 64;          // pass 0 tokens
    const int tile1 = base + wid * 64 + 256;    // pass 1 tokens
    const float* krow = key   + (size_t)b * NT * 16;
    const float* vrow = value + (size_t)b * NT * 16;
    const float L = 1.4426950408889634f;

    // G1: key tile 0 — issue immediately
    stage_tile(sw, krow + (size_t)tile0 * 16, lane);

    // q projection + v_w staging (W2 comes from __constant__)
    if (tid < 32) {
        const int w = tid;
        float acc = *bias;
        #pragma unroll
        for (int d = 0; d < 16; d++)
            acc = fmaf(query[b * 16 + d], W1[w * 16 + d], acc);
        scv[w].x = pack2(acc, 0.0f);
        scv[w].y = pack2(L * v_w[w], 0.0f);     // pre-scaled by log2(e)
    }
    __syncthreads();

    const float vbL = v_b[0] * L;

    // ---------- Phase A: scores + inline exp (no max pass: bounded scores) ----
    float e_[4];
    float csum = 0.0f;

    #pragma unroll
    for (int jp = 0; jp < 2; jp++) {
        cpwait0();
        __syncwarp();
        ull ka[8], kb[8];
        read_pair(bufc, lane, ka, kb);
        __syncwarp();

        if (jp == 0)
            stage_tile(sw, krow + (size_t)tile1 * 16, lane);   // G2: key tile 1
        else
            stage_tile(sw, vrow + (size_t)tile0 * 16, lane);   // G3: value tile A

        float a0 = vbL, a1 = vbL;
        #pragma unroll 4
        for (int w = 0; w < 32; w++) {
            const ulonglong2 cc = scv[w];      // one LDS.128: qproj pair + L*v_w
            ull acc0 = cc.x;
            ull acc1 = acc0;
            const float vwL = unpack2(cc.y).x;
            const ulonglong2* wr = &cW2q[w * 4];   // 128-bit constant loads
            ulonglong2 w01 = wr[0];
            pfma(acc0, ka[0], w01.x); pfma(acc1, kb[0], w01.x);
            pfma(acc0, ka[1], w01.y); pfma(acc1, kb[1], w01.y);
            ulonglong2 w23 = wr[1];
            pfma(acc0, ka[2], w23.x); pfma(acc1, kb[2], w23.x);
            pfma(acc0, ka[3], w23.y); pfma(acc1, kb[3], w23.y);
            ulonglong2 w45 = wr[2];
            pfma(acc0, ka[4], w45.x); pfma(acc1, kb[4], w45.x);
            pfma(acc0, ka[5], w45.y); pfma(acc1, kb[5], w45.y);
            ulonglong2 w67 = wr[3];
            pfma(acc0, ka[6], w67.x); pfma(acc1, kb[6], w67.x);
            pfma(acc0, ka[7], w67.y); pfma(acc1, kb[7], w67.y);

            const float2 h0 = unpack2(acc0);
            const float2 h1 = unpack2(acc1);
            const float t0h = tanhf_(h0.x + h0.y);
            const float t1h = tanhf_(h1.x + h1.y);
            a0 = fmaf(vwL, t0h, a0);
            a1 = fmaf(vwL, t1h, a1);
        }
        const float e0 = ex2f_(a0);        // exp(score), L pre-folded
        const float e1 = ex2f_(a1);
        e_[2 * jp + 0] = e0;
        e_[2 * jp + 1] = e1;
        csum += e0 + e1;
    }

    // ---------- EARLY publish of this CTA's sum (hides sibling skew) ----------
    {
        float cs = csum;
        #pragma unroll
        for (int o = 16; o > 0; o >>= 1)
            cs += __shfl_xor_sync(0xffffffffu, cs, o);
        if (lane == 0) ssum[wid] = cs;
    }
    __syncthreads();
    if (tid == 0) {
        g_scratch[cta * 18] = ssum[0] + ssum[1] + ssum[2] + ssum[3];
        red_release_add(&g_cnt1[b], 1);      // arrive: sum ready
    }

    // ---------- Value accumulation (two tiles, pipelined) ----------
    ull cv[8];
    #pragma unroll
    for (int i = 0; i < 8; i++) cv[i] = 0ull;

    {   // value tile A (tokens tile0+lane, tile0+lane+32)
        cpwait0();
        __syncwarp();
        ull va[8], vbr[8];
        read_pair(bufc, lane, va, vbr);
        __syncwarp();
        stage_tile(sw, vrow + (size_t)tile1 * 16, lane);       // G4: value tile B

        const ull ee0 = pack2(e_[0], e_[0]);
        const ull ee1 = pack2(e_[1], e_[1]);
        #pragma unroll
        for (int i = 0; i < 8; i++) {
            pfma(cv[i], ee0, va[i]);
            pfma(cv[i], ee1, vbr[i]);
        }
    }
    {   // value tile B (tokens tile1+lane, tile1+lane+32)
        cpwait0();
        __syncwarp();
        ull va[8], vbr[8];
        read_pair(bufc, lane, va, vbr);

        const ull ee2 = pack2(e_[2], e_[2]);
        const ull ee3 = pack2(e_[3], e_[3]);
        #pragma unroll
        for (int i = 0; i < 8; i++) {
            pfma(cv[i], ee2, va[i]);
            pfma(cv[i], ee3, vbr[i]);
        }
    }

    float cvf[16];
    #pragma unroll
    for (int i = 0; i < 8; i++) {
        float2 u = unpack2(cv[i]);
        cvf[2*i] = u.x; cvf[2*i+1] = u.y;
    }

    // ---------- Deterministic ctx reduction over 4 warps ----------
    #pragma unroll
    for (int o = 16; o > 0; o >>= 1) {
        #pragma unroll
        for (int i = 0; i < 16; i++)
            cvf[i] += __shfl_xor_sync(0xffffffffu, cvf[i], o);
    }
    if (lane == 0) {
        #pragma unroll
        for (int i = 0; i < 16; i++) sred[wid * 16 + i] = cvf[i];
    }
    __syncthreads();
    if (tid < 16) {
        float a = sred[tid];
        #pragma unroll
        for (int w = 1; w < 4; w++) a += sred[w * 16 + tid];
        g_scratch[cta * 18 + 1 + tid] = a;   // ctx partial
    }
    __syncthreads();

    // ---------- Spin on sums (usually already satisfied) ----------
    if (tid == 0) {
        while (ld_acquire(&g_cnt1[b]) < NCHUNK) __nanosleep(32);
        const float* gs = g_scratch + b * (NCHUNK * 18);
        float total = 0.0f;
        #pragma unroll
        for (int c = 0; c < NCHUNK; c++) total += gs[c * 18];   // fixed order
        sbc[0] = rcpf_(total);
    }
    __syncthreads();
    const float inv = sbc[0];

    float* ao = out_attn + (size_t)b * NT;
    ao[tile0 + lane]      = e_[0] * inv;
    ao[tile0 + lane + 32] = e_[1] * inv;
    ao[tile1 + lane]      = e_[2] * inv;
    ao[tile1 + lane + 32] = e_[3] * inv;

    // ---------- Last arriver writes ctx + resets (no second spin) ----------
    __syncthreads();           // ctx partials + attn writes done CTA-wide
    if (tid == 0) {
        const int prev = atomicAdd(&g_cnt2[b], 1);   // after cnt1 spin: reset-safe
        slast = (prev == NCHUNK - 1);
        if (slast) __threadfence();                  // acquire partials
    }
    __syncthreads();
    if (slast) {
        if (tid < 16) {
            const float* gs = g_scratch + b * (NCHUNK * 18);
            float acc = 0.0f;
            #pragma unroll
            for (int c = 0; c < NCHUNK; c++) acc += gs[c * 18 + 1 + tid];
            out_ctx[b * 16 + tid] = acc * inv;
        }
        __syncthreads();
        if (tid == 0) {        // every sibling already passed both counters
            g_cnt1[b] = 0;
            __threadfence();
            g_cnt2[b] = 0;
        }
    }
}

extern "C" void kernel_launch(void* const* d_in, const int* in_sizes, int n_in,
                              void* d_out, int out_size) {
    const float* query = (const float*)d_in[0];
    const float* key   = (const float*)d_in[1];
    const float* value = (const float*)d_in[2];
    const float* W1    = (const float*)d_in[3];
    const float* W2    = (const float*)d_in[4];
    const float* bias  = (const float*)d_in[5];
    const float* v_w   = (const float*)d_in[6];
    const float* v_b   = (const float*)d_in[7];

    float* out_ctx  = (float*)d_out;            // [B,1,16]
    float* out_attn = (float*)d_out + NB * 16;  // [B,T]

    // Single constant upload (W2 only)
    cudaMemcpyToSymbolAsync(cW2q, W2, 32 * 16 * sizeof(float), 0,
                            cudaMemcpyDeviceToDevice);

    attn_fused<<<NB * NCHUNK, K1_NTH>>>(query, key, value, W1,
                                        bias, v_w, v_b, out_ctx, out_attn);
}